// round 1
// baseline (speedup 1.0000x reference)
#include <cuda_runtime.h>

#define TWO_PI_F 6.283185307179586f
#define NROT 8
#define C_DIM 128
#define KS 5
#define PATCH 25            // 5*5
#define TPB 200             // i(8) * yx(25)
#define CIN_CHUNK 32
#define CIN_CHUNKS 4        // 32*4 = 128

__global__ __launch_bounds__(TPB)
void gk_fused_kernel(const float* __restrict__ in_H,
                     const float* __restrict__ out_H,
                     const float* __restrict__ weight,
                     const float* __restrict__ grid_Rn,
                     const float* __restrict__ mask,
                     float* __restrict__ out)
{
    const int co = blockIdx.x;           // original Cout index (output axis 2)
    const int o  = blockIdx.y;           // out_H index (output axis 1)
    const int ci_base = blockIdx.z * CIN_CHUNK;

    const int tid = threadIdx.x;         // 0..199
    const int i   = tid / PATCH;         // in_H index (output axis 3)
    const int p   = tid % PATCH;         // y*5 + x

    // ---- per-(o,i): Gk interpolation indices ----
    const float outH = out_H[o];
    const float theta = in_H[i] - outH;                 // out_inv + in_H
    const float tmod  = theta - floorf(theta * (1.0f / TWO_PI_F)) * TWO_PI_F; // jnp.mod
    const float pos   = tmod * ((float)NROT / TWO_PI_F);
    const float fl    = floorf(pos);
    int i0 = ((int)fl) % NROT;           // pos >= 0, so no negative fixup needed
    if (i0 >= NROT) i0 -= NROT;          // guard pos==8.0 edge
    const int i1 = (i0 + 1) & (NROT - 1);
    const float frac = pos - fl;

    // ---- per-(o,p): rotated bilinear sample coefficients ----
    const float ang = -outH;
    const float cc = cosf(ang), ss = sinf(ang);
    const float X = grid_Rn[p];
    const float Y = grid_Rn[PATCH + p];
    const float gx = cc * X - ss * Y;
    const float gy = ss * X + cc * Y;
    const float sx = (gx + 1.0f) * 0.5f * (float)(KS - 1);
    const float sy = (gy + 1.0f) * 0.5f * (float)(KS - 1);
    const float fxf = floorf(sx), fyf = floorf(sy);
    const float fx = sx - fxf, fy = sy - fyf;           // from UNclamped floor (ref behavior)
    int x0 = (int)fxf; x0 = min(max(x0, 0), KS - 1);
    int y0 = (int)fyf; y0 = min(max(y0, 0), KS - 1);
    const int x1 = min(x0 + 1, KS - 1);
    const int y1 = min(y0 + 1, KS - 1);

    const float m = mask[p];
    const float w00 = (1.0f - fy) * (1.0f - fx) * m;
    const float w01 = (1.0f - fy) * fx * m;
    const float w10 = fy * (1.0f - fx) * m;
    const float w11 = fy * fx * m;

    // fold Gk lerp into 8 corner coefficients
    const float a = 1.0f - frac, b = frac;
    const float c00a = w00 * a, c01a = w01 * a, c10a = w10 * a, c11a = w11 * a;
    const float c00b = w00 * b, c01b = w01 * b, c10b = w10 * b, c11b = w11 * b;

    const int i00 = y0 * KS + x0;
    const int i01 = y0 * KS + x1;
    const int i10 = y1 * KS + x0;
    const int i11 = y1 * KS + x1;

    // weight[g][co][ci][p] flat = ((g*128 + co)*128 + ci)*25 + p
    const float* base0 = weight + (size_t)((i0 * C_DIM + co) * C_DIM + ci_base) * PATCH;
    const float* base1 = weight + (size_t)((i1 * C_DIM + co) * C_DIM + ci_base) * PATCH;

    // out[ci][o][co][i][y][x] flat = ((ci*8 + o)*128 + co)*200 + tid
    float* outp = out + ((size_t)(ci_base * NROT + o) * C_DIM + co) * (NROT * PATCH) + tid;
    const size_t out_stride = (size_t)NROT * C_DIM * NROT * PATCH;  // cin stride = 204800

#pragma unroll 4
    for (int ci = 0; ci < CIN_CHUNK; ++ci) {
        const float* p0 = base0 + ci * PATCH;
        const float* p1 = base1 + ci * PATCH;
        float v = c00a * __ldg(p0 + i00) + c01a * __ldg(p0 + i01)
                + c10a * __ldg(p0 + i10) + c11a * __ldg(p0 + i11)
                + c00b * __ldg(p1 + i00) + c01b * __ldg(p1 + i01)
                + c10b * __ldg(p1 + i10) + c11b * __ldg(p1 + i11);
        outp[(size_t)ci * out_stride] = v;
    }
}

extern "C" void kernel_launch(void* const* d_in, const int* in_sizes, int n_in,
                              void* d_out, int out_size)
{
    const float* in_H    = (const float*)d_in[0];
    const float* out_H   = (const float*)d_in[1];
    const float* weight  = (const float*)d_in[2];
    // d_in[3] = grid_H (unused by the math beyond N=8, which is compile-time)
    const float* grid_Rn = (const float*)d_in[4];
    const float* mask    = (const float*)d_in[5];
    float* out = (float*)d_out;

    dim3 grid(C_DIM, NROT, CIN_CHUNKS);   // (cout=128, o=8, cin chunks=4)
    gk_fused_kernel<<<grid, TPB>>>(in_H, out_H, weight, grid_Rn, mask, out);
}

// round 2
// speedup vs baseline: 1.0608x; 1.0608x over previous
#include <cuda_runtime.h>

#define TWO_PI_F 6.283185307179586f
#define NROT 8
#define C_DIM 128
#define KS 5
#define PATCH 25            // 5*5
#define IP 200              // i(8) * yx(25)
#define TPB 400             // 200 (i,p) combos x 2 ci-halves
#define CIN_CHUNK 32
#define CIN_CHUNKS 4
#define SLAB 800            // 32 ci * 25 q floats per g-slab in smem

__global__ __launch_bounds__(TPB)
void gk_fused_smem_kernel(const float* __restrict__ in_H,
                          const float* __restrict__ out_H,
                          const float* __restrict__ weight,
                          const float* __restrict__ grid_Rn,
                          const float* __restrict__ mask,
                          float* __restrict__ out)
{
    __shared__ float sw[NROT * SLAB];   // [g][ci(32)][q(25)] = 25600 B

    const int co      = blockIdx.x;
    const int o       = blockIdx.y;
    const int ci_base = blockIdx.z * CIN_CHUNK;
    const int tid     = threadIdx.x;

    // ---------------- fill: 8 g-slabs of (32 ci x 25 q) via float4 ----------------
    // per g: 800 floats = 200 float4, contiguous in gmem; 16B-aligned
    // (base elem offset = ((g*128+co)*128+ci_base)*25, a multiple of 4 since ci_base%4==0)
    {
        const float4* __restrict__ w4 = (const float4*)weight;
#pragma unroll
        for (int it = 0; it < 4; ++it) {
            int f   = tid + it * TPB;          // 0..1599 float4 index
            int g   = f / 200;
            int r   = f - g * 200;             // float4 within slab
            size_t gbase4 = ((size_t)((g * C_DIM + co) * C_DIM + ci_base) * PATCH) >> 2;
            float4 v = w4[gbase4 + r];
            *(float4*)&sw[g * SLAB + r * 4] = v;
        }
    }

    // ---------------- per-thread coefficients ----------------
    const int ip    = tid % IP;        // (i,p)
    const int chalf = tid / IP;        // 0 or 1
    const int i     = ip / PATCH;
    const int p     = ip % PATCH;

    const float outH  = out_H[o];
    const float theta = in_H[i] - outH;
    const float tmod  = theta - floorf(theta * (1.0f / TWO_PI_F)) * TWO_PI_F;
    const float pos   = tmod * ((float)NROT / TWO_PI_F);
    const float fl    = floorf(pos);
    int g0 = ((int)fl) % NROT;
    if (g0 >= NROT) g0 -= NROT;
    const int g1 = (g0 + 1) & (NROT - 1);
    const float frac = pos - fl;

    const float ang = -outH;
    const float cc = cosf(ang), ss = sinf(ang);
    const float X = grid_Rn[p];
    const float Y = grid_Rn[PATCH + p];
    const float gx = cc * X - ss * Y;
    const float gy = ss * X + cc * Y;
    const float sx = (gx + 1.0f) * 0.5f * (float)(KS - 1);
    const float sy = (gy + 1.0f) * 0.5f * (float)(KS - 1);
    const float fxf = floorf(sx), fyf = floorf(sy);
    const float fx = sx - fxf, fy = sy - fyf;
    int x0 = (int)fxf; x0 = min(max(x0, 0), KS - 1);
    int y0 = (int)fyf; y0 = min(max(y0, 0), KS - 1);
    const int x1 = min(x0 + 1, KS - 1);
    const int y1 = min(y0 + 1, KS - 1);

    const float m = mask[p];
    const float w00 = (1.0f - fy) * (1.0f - fx) * m;
    const float w01 = (1.0f - fy) * fx * m;
    const float w10 = fy * (1.0f - fx) * m;
    const float w11 = fy * fx * m;
    const float a = 1.0f - frac, b = frac;
    const float c00a = w00 * a, c01a = w01 * a, c10a = w10 * a, c11a = w11 * a;
    const float c00b = w00 * b, c01b = w01 * b, c10b = w10 * b, c11b = w11 * b;

    const int q00 = y0 * KS + x0;
    const int q01 = y0 * KS + x1;
    const int q10 = y1 * KS + x0;
    const int q11 = y1 * KS + x1;

    __syncthreads();

    // ---------------- compute: 16 ci per thread ----------------
    const int ci0 = chalf * (CIN_CHUNK / 2);               // local ci start (0 or 16)
    const float* s0 = &sw[g0 * SLAB + ci0 * PATCH];
    const float* s1 = &sw[g1 * SLAB + ci0 * PATCH];

    // out[ci][o][co][ip]: ip fastest (coalesced), ci stride = 8*128*200
    float* outp = out
        + ((size_t)((ci_base + ci0) * NROT + o) * C_DIM + co) * IP + ip;
    const size_t ostride = (size_t)NROT * C_DIM * IP;      // 204800

#pragma unroll
    for (int j = 0; j < CIN_CHUNK / 2; ++j) {
        const float* p0 = s0 + j * PATCH;
        const float* p1 = s1 + j * PATCH;
        float v = c00a * p0[q00] + c01a * p0[q01]
                + c10a * p0[q10] + c11a * p0[q11]
                + c00b * p1[q00] + c01b * p1[q01]
                + c10b * p1[q10] + c11b * p1[q11];
        outp[(size_t)j * ostride] = v;
    }
}

extern "C" void kernel_launch(void* const* d_in, const int* in_sizes, int n_in,
                              void* d_out, int out_size)
{
    const float* in_H    = (const float*)d_in[0];
    const float* out_H   = (const float*)d_in[1];
    const float* weight  = (const float*)d_in[2];
    const float* grid_Rn = (const float*)d_in[4];
    const float* mask    = (const float*)d_in[5];
    float* out = (float*)d_out;

    dim3 grid(C_DIM, NROT, CIN_CHUNKS);   // (cout, o, ci chunks)
    gk_fused_smem_kernel<<<grid, TPB>>>(in_H, out_H, weight, grid_Rn, mask, out);
}